// round 1
// baseline (speedup 1.0000x reference)
#include <cuda_runtime.h>
#include <cuda_bf16.h>
#include <math.h>

#define HD   20
#define TPB  192
#define CH_L 256
#define CH_W 64

typedef unsigned long long ull;

__device__ __forceinline__ float tanh_fast(float x) {
    float y; asm("tanh.approx.f32 %0, %1;" : "=f"(y) : "f"(x)); return y;
}
__device__ __forceinline__ ull pack2(float a, float b) {
    ull r; asm("mov.b64 %0, {%1,%2};" : "=l"(r) : "f"(a), "f"(b)); return r;
}
__device__ __forceinline__ float2 unpack2(ull p) {
    float2 v; asm("mov.b64 {%0,%1}, %2;" : "=f"(v.x), "=f"(v.y) : "l"(p)); return v;
}
__device__ __forceinline__ ull ffma2(ull a, ull b, ull c) {
    ull r; asm("fma.rn.f32x2 %0, %1, %2, %3;" : "=l"(r) : "l"(a), "l"(b), "l"(c)); return r;
}

// Block = 192 threads. Threads 0..95: layer-1 (3 warps), 96..191: layer-2 (3 warps).
// Within a layer group: warp wl handles units [8*wl, 8*wl+8); lane = 4*(u-8*wl)+gate.
// Gate order (PyTorch): i,f,g,o = weight rows gate*20+u.
__global__ __launch_bounds__(TPB)
void lstm_opt_kernel(const float* __restrict__ grad,
                     const float* __restrict__ Wih0, const float* __restrict__ Whh0,
                     const float* __restrict__ bih0, const float* __restrict__ bhh0,
                     const float* __restrict__ Wih1, const float* __restrict__ Whh1,
                     const float* __restrict__ bih1, const float* __restrict__ bhh1,
                     const float* __restrict__ Wlin, const float* __restrict__ blin,
                     float* __restrict__ out, int N, int out_size)
{
    __shared__ __align__(16) float2 xbuf[CH_L + 2 * CH_W];
    __shared__ __align__(16) float h0buf[2][32];
    __shared__ __align__(16) float y0buf[2][32];
    __shared__ __align__(16) float h1buf[2][32];
    __shared__ float outpart[2][4];

    const int tid   = threadIdx.x;
    const int layer = tid / 96;          // warp-uniform (96 = 3 warps)
    const int lt    = tid % 96;
    const int wl    = lt >> 5;           // warp within layer 0..2
    const int lane  = lt & 31;
    const int u     = wl * 8 + (lane >> 2);
    const int gate  = lane & 3;
    const bool act_th = (u < HD);
    const int r     = act_th ? gate * HD + u : 0;

    // ---- preload weights into registers (packed f32x2 pairs) ----
    ull whh[10], win[10];
    float wx0 = 0.f, wx1 = 0.f, bias, wlin_u = 0.f;
    if (layer == 0) {
        #pragma unroll
        for (int k = 0; k < 10; k++)
            whh[k] = pack2(Whh0[r * HD + 2 * k], Whh0[r * HD + 2 * k + 1]);
        #pragma unroll
        for (int k = 0; k < 10; k++) win[k] = 0ull;
        wx0 = Wih0[r * 2 + 0];
        wx1 = Wih0[r * 2 + 1];
        bias = bih0[r] + bhh0[r];
    } else {
        #pragma unroll
        for (int k = 0; k < 10; k++)
            whh[k] = pack2(Whh1[r * HD + 2 * k], Whh1[r * HD + 2 * k + 1]);
        #pragma unroll
        for (int k = 0; k < 10; k++)
            win[k] = pack2(Wih1[r * HD + 2 * k], Wih1[r * HD + 2 * k + 1]);
        bias = bih1[r] + bhh1[r];
        if (act_th) wlin_u = Wlin[u];
    }
    const float blinv = blin[0];

    // ---- chunk ranges: layer-2 warms up from s2, layer-1 from s1 ----
    const int c         = blockIdx.x;
    const int start_out = c * CH_L;
    if (start_out >= N) return;
    const int end_out = min(N, start_out + CH_L);
    const int s2      = max(0, start_out - CH_W);
    const int s1      = max(0, s2 - CH_W);
    const int span    = end_out - s1;

    // ---- preprocess grad -> (log, sign) features into smem ----
    for (int i = tid; i < span; i += TPB) {
        float g  = grad[s1 + i];
        float lg = logf(fabsf(g) + 1e-8f) * 0.1f;
        lg = fminf(1.f, fmaxf(-1.f, lg));
        float sg = fminf(1.f, fmaxf(-1.f, g * 22026.4657948067f)); // exp(10)
        xbuf[i] = make_float2(lg, sg);
    }
    if (tid < 32) {
        h0buf[0][tid] = 0.f; h0buf[1][tid] = 0.f;
        y0buf[0][tid] = 0.f; y0buf[1][tid] = 0.f;
        h1buf[0][tid] = 0.f; h1buf[1][tid] = 0.f;
    }
    if (tid < 8) (&outpart[0][0])[tid] = 0.f;
    __syncthreads();

    float cstate = 0.f, hlast = 0.f;
    const int nIter = span + 2;   // +1 pipeline drain (layer-2), +1 output drain

    for (int i = 0; i < nIter; ++i) {
        const int tt = s1 + i;    // layer-1 time
        const int t2 = tt - 1;    // layer-2 time (one step behind)

        if (layer == 0) {
            if (tt < end_out) {
                const int p1 = tt & 1;
                ull acc = pack2(bias, 0.f);
                const ull* hb = (const ull*)h0buf[p1 ^ 1];
                #pragma unroll
                for (int k = 0; k < 10; k++) acc = ffma2(whh[k], hb[k], acc);
                float2 sv = unpack2(acc);
                float2 x  = xbuf[i];
                float pre = sv.x + sv.y + wx0 * x.x + wx1 * x.y;
                // sigmoid(z)=0.5*(1+tanh(z/2)); gate 2 (g) uses tanh directly
                float arg = (gate == 2) ? pre : 0.5f * pre;
                float th  = tanh_fast(arg);
                float a   = (gate == 2) ? th : fmaf(th, 0.5f, 0.5f);
                // gather i,f,g,o within the 4-lane unit group; lane gate==0 sees
                // i=a, f=v1, g=v2, o=v3 directly (others compute garbage, unused)
                float v1 = __shfl_xor_sync(0xffffffffu, a, 1);
                float v2 = __shfl_xor_sync(0xffffffffu, a, 2);
                float v3 = __shfl_xor_sync(0xffffffffu, v1, 2);
                cstate = fmaf(v1, cstate, a * v2);       // f*c + i*g
                float hh = v3 * tanh_fast(cstate);       // o*tanh(c)
                if (gate == 0 && act_th) {
                    hlast = hh;
                    h0buf[p1][u] = hh;
                    y0buf[p1][u] = hh;
                }
            }
            // idle lane (u==20 group) drains the output partials, 2 steps behind
            if (tid == 80) {
                const int tout = tt - 2;
                if (tout >= start_out && tout < end_out) {
                    const int pp = tout & 1;
                    float sum = outpart[pp][0] + outpart[pp][1] + outpart[pp][2];
                    out[tout] = (sum + blinv) * 0.01f;
                }
            }
        } else {
            if (t2 >= s2 && t2 < end_out) {
                const int p2 = t2 & 1;
                ull acc = pack2(bias, 0.f);
                const ull* hb = (const ull*)h1buf[p2 ^ 1];
                const ull* yb = (const ull*)y0buf[p2];   // y0[t2], written last iter
                #pragma unroll
                for (int k = 0; k < 10; k++) acc = ffma2(whh[k], hb[k], acc);
                #pragma unroll
                for (int k = 0; k < 10; k++) acc = ffma2(win[k], yb[k], acc);
                float2 sv = unpack2(acc);
                float pre = sv.x + sv.y;
                float arg = (gate == 2) ? pre : 0.5f * pre;
                float th  = tanh_fast(arg);
                float a   = (gate == 2) ? th : fmaf(th, 0.5f, 0.5f);
                float v1 = __shfl_xor_sync(0xffffffffu, a, 1);
                float v2 = __shfl_xor_sync(0xffffffffu, a, 2);
                float v3 = __shfl_xor_sync(0xffffffffu, v1, 2);
                cstate = fmaf(v1, cstate, a * v2);
                float hh = v3 * tanh_fast(cstate);
                float part = 0.f;
                if (gate == 0 && act_th) {
                    hlast = hh;
                    h1buf[p2][u] = hh;
                    part = hh * wlin_u;                  // linear head partial
                }
                part += __shfl_xor_sync(0xffffffffu, part, 4);
                part += __shfl_xor_sync(0xffffffffu, part, 8);
                part += __shfl_xor_sync(0xffffffffu, part, 16);
                if (lane == 0) outpart[p2][wl] = part;
            }
        }
        __syncthreads();
    }

    // final (h,c) states from the last chunk: layout [h0, h1, c0, c1] after update
    if (end_out == N && out_size >= N + 80 && gate == 0 && act_th) {
        if (layer == 0) { out[N + u]      = hlast; out[N + 40 + u] = cstate; }
        else            { out[N + 20 + u] = hlast; out[N + 60 + u] = cstate; }
    }
}

extern "C" void kernel_launch(void* const* d_in, const int* in_sizes, int n_in,
                              void* d_out, int out_size) {
    const float* grad = (const float*)d_in[0];
    const float* Wih0 = (const float*)d_in[1];
    const float* Whh0 = (const float*)d_in[2];
    const float* bih0 = (const float*)d_in[3];
    const float* bhh0 = (const float*)d_in[4];
    const float* Wih1 = (const float*)d_in[5];
    const float* Whh1 = (const float*)d_in[6];
    const float* bih1 = (const float*)d_in[7];
    const float* bhh1 = (const float*)d_in[8];
    const float* Wlin = (const float*)d_in[9];
    const float* blin = (const float*)d_in[10];

    int N = in_sizes[0];
    int grid = (N + CH_L - 1) / CH_L;
    lstm_opt_kernel<<<grid, TPB>>>(grad, Wih0, Whh0, bih0, bhh0,
                                   Wih1, Whh1, bih1, bhh1, Wlin, blin,
                                   (float*)d_out, N, out_size);
}

// round 2
// speedup vs baseline: 1.3632x; 1.3632x over previous
#include <cuda_runtime.h>
#include <cuda_bf16.h>
#include <math.h>

#define HD   20
#define TPB  192
#define CH_L 128
#define CH_W 32

typedef unsigned long long ull;

__device__ __forceinline__ float tanh_fast(float x) {
    float y; asm("tanh.approx.f32 %0, %1;" : "=f"(y) : "f"(x)); return y;
}
__device__ __forceinline__ ull pack2(float a, float b) {
    ull r; asm("mov.b64 %0, {%1,%2};" : "=l"(r) : "f"(a), "f"(b)); return r;
}
__device__ __forceinline__ float2 unpack2(ull p) {
    float2 v; asm("mov.b64 {%0,%1}, %2;" : "=f"(v.x), "=f"(v.y) : "l"(p)); return v;
}
__device__ __forceinline__ ull ffma2(ull a, ull b, ull c) {
    ull r; asm("fma.rn.f32x2 %0, %1, %2, %3;" : "=l"(r) : "l"(a), "l"(b), "l"(c)); return r;
}

// Block = 192 threads. Threads 0..95: layer-1 (3 warps), 96..191: layer-2 (3 warps).
// Within a layer group: warp wl handles units [8*wl, 8*wl+8); lane = 4*(u-8*wl)+gate.
// Gate order (PyTorch): i,f,g,o = weight rows gate*20+u.
__global__ __launch_bounds__(TPB)
void lstm_opt_kernel(const float* __restrict__ grad,
                     const float* __restrict__ Wih0, const float* __restrict__ Whh0,
                     const float* __restrict__ bih0, const float* __restrict__ bhh0,
                     const float* __restrict__ Wih1, const float* __restrict__ Whh1,
                     const float* __restrict__ bih1, const float* __restrict__ bhh1,
                     const float* __restrict__ Wlin, const float* __restrict__ blin,
                     float* __restrict__ out, int N, int out_size)
{
    __shared__ __align__(16) float2 xbuf[CH_L + 2 * CH_W];
    __shared__ __align__(16) float h0buf[2][32];
    __shared__ __align__(16) float y0buf[2][32];
    __shared__ __align__(16) float h1buf[2][32];
    __shared__ float outpart[2][4];

    const int tid   = threadIdx.x;
    const int layer = tid / 96;          // warp-uniform (96 = 3 warps)
    const int lt    = tid % 96;
    const int wl    = lt >> 5;           // warp within layer 0..2
    const int lane  = lt & 31;
    const int u     = wl * 8 + (lane >> 2);
    const int gate  = lane & 3;
    const bool act_th = (u < HD);
    const int r     = act_th ? gate * HD + u : 0;

    // ---- preload weights into registers (packed f32x2 pairs) ----
    ull whh[10], win[10];
    float wx0 = 0.f, wx1 = 0.f, bias, wlin_u = 0.f;
    if (layer == 0) {
        #pragma unroll
        for (int k = 0; k < 10; k++)
            whh[k] = pack2(Whh0[r * HD + 2 * k], Whh0[r * HD + 2 * k + 1]);
        #pragma unroll
        for (int k = 0; k < 10; k++) win[k] = 0ull;
        wx0 = Wih0[r * 2 + 0];
        wx1 = Wih0[r * 2 + 1];
        bias = bih0[r] + bhh0[r];
    } else {
        #pragma unroll
        for (int k = 0; k < 10; k++)
            whh[k] = pack2(Whh1[r * HD + 2 * k], Whh1[r * HD + 2 * k + 1]);
        #pragma unroll
        for (int k = 0; k < 10; k++)
            win[k] = pack2(Wih1[r * HD + 2 * k], Wih1[r * HD + 2 * k + 1]);
        bias = bih1[r] + bhh1[r];
        if (act_th) wlin_u = Wlin[u];
    }
    const float blinv = blin[0];

    // ---- chunk ranges: layer-2 warms up from s2, layer-1 from s1 ----
    const int c         = blockIdx.x;
    const int start_out = c * CH_L;
    if (start_out >= N) return;
    const int end_out = min(N, start_out + CH_L);
    const int s2      = max(0, start_out - CH_W);
    const int s1      = max(0, s2 - CH_W);
    const int span    = end_out - s1;

    // ---- preprocess grad -> (log, sign) features into smem ----
    for (int i = tid; i < span; i += TPB) {
        float g  = grad[s1 + i];
        float lg = logf(fabsf(g) + 1e-8f) * 0.1f;
        lg = fminf(1.f, fmaxf(-1.f, lg));
        float sg = fminf(1.f, fmaxf(-1.f, g * 22026.4657948067f)); // exp(10)
        xbuf[i] = make_float2(lg, sg);
    }
    if (tid < 32) {
        h0buf[0][tid] = 0.f; h0buf[1][tid] = 0.f;
        y0buf[0][tid] = 0.f; y0buf[1][tid] = 0.f;
        h1buf[0][tid] = 0.f; h1buf[1][tid] = 0.f;
    }
    if (tid < 8) (&outpart[0][0])[tid] = 0.f;
    __syncthreads();

    float cstate = 0.f, hlast = 0.f;
    const int nIter = span + 2;   // +1 pipeline drain (layer-2), +1 output drain

    for (int i = 0; i < nIter; ++i) {
        const int tt = s1 + i;    // layer-1 time
        const int t2 = tt - 1;    // layer-2 time (one step behind)

        if (layer == 0) {
            if (tt < end_out) {
                const int p1 = tt & 1;
                float2 x  = xbuf[i];
                // x-term + bias folded into acc init: off the h-dependency chain
                float base = fmaf(wx0, x.x, fmaf(wx1, x.y, bias));
                ull acc0 = pack2(base, 0.f);
                ull acc1 = pack2(0.f, 0.f);
                const ull* hb = (const ull*)h0buf[p1 ^ 1];
                #pragma unroll
                for (int k = 0; k < 5; k++) {
                    acc0 = ffma2(whh[k],     hb[k],     acc0);
                    acc1 = ffma2(whh[k + 5], hb[k + 5], acc1);
                }
                float2 s0 = unpack2(acc0);
                float2 s1v = unpack2(acc1);
                float pre = (s0.x + s0.y) + (s1v.x + s1v.y);
                // sigmoid(z)=0.5*(1+tanh(z/2)); gate 2 (g) uses tanh directly
                float arg = (gate == 2) ? pre : 0.5f * pre;
                float th  = tanh_fast(arg);
                float a   = (gate == 2) ? th : fmaf(th, 0.5f, 0.5f);
                // independent gathers: lane gate==0 sees i=a, f=v1, g=v2, o=v3
                float v1 = __shfl_xor_sync(0xffffffffu, a, 1);
                float v2 = __shfl_xor_sync(0xffffffffu, a, 2);
                float v3 = __shfl_xor_sync(0xffffffffu, a, 3);
                cstate = fmaf(v1, cstate, a * v2);       // f*c + i*g
                float hh = v3 * tanh_fast(cstate);       // o*tanh(c)
                if (gate == 0 && act_th) {
                    hlast = hh;
                    h0buf[p1][u] = hh;
                    y0buf[p1][u] = hh;
                }
            }
            // idle lane (u==20 group) drains the output partials, 2 steps behind
            if (tid == 80) {
                const int tout = tt - 2;
                if (tout >= start_out && tout < end_out) {
                    const int pp = tout & 1;
                    float sum = outpart[pp][0] + outpart[pp][1] + outpart[pp][2];
                    out[tout] = (sum + blinv) * 0.01f;
                }
            }
        } else {
            if (t2 >= s2 && t2 < end_out) {
                const int p2 = t2 & 1;
                ull acc0 = pack2(bias, 0.f);
                ull acc1 = pack2(0.f, 0.f);
                const ull* hb = (const ull*)h1buf[p2 ^ 1];
                const ull* yb = (const ull*)y0buf[p2];   // y0[t2], written last iter
                #pragma unroll
                for (int k = 0; k < 10; k++) {
                    acc0 = ffma2(whh[k], hb[k], acc0);   // h-chain
                    acc1 = ffma2(win[k], yb[k], acc1);   // y-chain (independent)
                }
                float2 s0 = unpack2(acc0);
                float2 s1v = unpack2(acc1);
                float pre = (s0.x + s0.y) + (s1v.x + s1v.y);
                float arg = (gate == 2) ? pre : 0.5f * pre;
                float th  = tanh_fast(arg);
                float a   = (gate == 2) ? th : fmaf(th, 0.5f, 0.5f);
                float v1 = __shfl_xor_sync(0xffffffffu, a, 1);
                float v2 = __shfl_xor_sync(0xffffffffu, a, 2);
                float v3 = __shfl_xor_sync(0xffffffffu, a, 3);
                cstate = fmaf(v1, cstate, a * v2);
                float hh = v3 * tanh_fast(cstate);
                float part = 0.f;
                if (gate == 0 && act_th) {
                    hlast = hh;
                    h1buf[p2][u] = hh;
                    part = hh * wlin_u;                  // linear head partial
                }
                part += __shfl_xor_sync(0xffffffffu, part, 4);
                part += __shfl_xor_sync(0xffffffffu, part, 8);
                part += __shfl_xor_sync(0xffffffffu, part, 16);
                if (lane == 0) outpart[p2][wl] = part;
            }
        }
        __syncthreads();
    }

    // final (h,c) states from the last chunk: layout [h0, h1, c0, c1] after update
    if (end_out == N && out_size >= N + 80 && gate == 0 && act_th) {
        if (layer == 0) { out[N + u]      = hlast; out[N + 40 + u] = cstate; }
        else            { out[N + 20 + u] = hlast; out[N + 60 + u] = cstate; }
    }
}

extern "C" void kernel_launch(void* const* d_in, const int* in_sizes, int n_in,
                              void* d_out, int out_size) {
    const float* grad = (const float*)d_in[0];
    const float* Wih0 = (const float*)d_in[1];
    const float* Whh0 = (const float*)d_in[2];
    const float* bih0 = (const float*)d_in[3];
    const float* bhh0 = (const float*)d_in[4];
    const float* Wih1 = (const float*)d_in[5];
    const float* Whh1 = (const float*)d_in[6];
    const float* bih1 = (const float*)d_in[7];
    const float* bhh1 = (const float*)d_in[8];
    const float* Wlin = (const float*)d_in[9];
    const float* blin = (const float*)d_in[10];

    int N = in_sizes[0];
    int grid = (N + CH_L - 1) / CH_L;
    lstm_opt_kernel<<<grid, TPB>>>(grad, Wih0, Whh0, bih0, bhh0,
                                   Wih1, Whh1, bih1, bhh1, Wlin, blin,
                                   (float*)d_out, N, out_size);
}

// round 3
// speedup vs baseline: 1.5789x; 1.1583x over previous
#include <cuda_runtime.h>
#include <cuda_bf16.h>
#include <math.h>

#define HD       20
#define TPB      192
#define CH_W     24
#define XBUF_MAX 176

typedef unsigned long long ull;

__device__ __forceinline__ float tanh_fast(float x) {
    float y; asm("tanh.approx.f32 %0, %1;" : "=f"(y) : "f"(x)); return y;
}
__device__ __forceinline__ ull pack2(float a, float b) {
    ull r; asm("mov.b64 %0, {%1,%2};" : "=l"(r) : "f"(a), "f"(b)); return r;
}
__device__ __forceinline__ float2 unpack2(ull p) {
    float2 v; asm("mov.b64 {%0,%1}, %2;" : "=f"(v.x), "=f"(v.y) : "l"(p)); return v;
}
__device__ __forceinline__ ull ffma2(ull a, ull b, ull c) {
    ull r; asm("fma.rn.f32x2 %0, %1, %2, %3;" : "=l"(r) : "l"(a), "l"(b), "l"(c)); return r;
}

// 192 threads: tid 0..95 = layer-1 (warps 0-2), 96..191 = layer-2 (warps 3-5).
// Row lanes: warp wl, lane = 4*(u - 8*wl) + gate, rows r = gate*20+u (PyTorch i,f,g,o).
// Idle lanes 16..31 of layer-1 warp 2 compute the Wlin head + output store.
__global__ __launch_bounds__(TPB)
void lstm_opt_kernel(const float* __restrict__ grad,
                     const float* __restrict__ Wih0, const float* __restrict__ Whh0,
                     const float* __restrict__ bih0, const float* __restrict__ bhh0,
                     const float* __restrict__ Wih1, const float* __restrict__ Whh1,
                     const float* __restrict__ bih1, const float* __restrict__ bhh1,
                     const float* __restrict__ Wlin, const float* __restrict__ blin,
                     float* __restrict__ out, int N, int out_size, int chl)
{
    __shared__ __align__(16) float2 xbuf[XBUF_MAX];
    __shared__ __align__(16) float h0buf[2][32];
    __shared__ __align__(16) float h1buf[2][32];

    const int tid   = threadIdx.x;
    const int layer = tid / 96;
    const int lt    = tid % 96;
    const int wl    = lt >> 5;
    const int lane  = lt & 31;
    const int u     = wl * 8 + (lane >> 2);
    const int gate  = lane & 3;
    const bool act  = (u < HD);
    const int r     = act ? gate * HD + u : 0;
    const unsigned rmask = (wl == 2) ? 0x0000FFFFu : 0xFFFFFFFFu;

    // ---- weights in registers (f32x2 packed) ----
    ull whh[10], win[10];
    float wx0 = 0.f, wx1 = 0.f, bias;
    if (layer == 0) {
        #pragma unroll
        for (int k = 0; k < 10; k++)
            whh[k] = pack2(Whh0[r * HD + 2 * k], Whh0[r * HD + 2 * k + 1]);
        wx0 = Wih0[r * 2 + 0];
        wx1 = Wih0[r * 2 + 1];
        bias = bih0[r] + bhh0[r];
        #pragma unroll
        for (int k = 0; k < 10; k++) win[k] = 0ull;
    } else {
        #pragma unroll
        for (int k = 0; k < 10; k++)
            whh[k] = pack2(Whh1[r * HD + 2 * k], Whh1[r * HD + 2 * k + 1]);
        #pragma unroll
        for (int k = 0; k < 10; k++)
            win[k] = pack2(Wih1[r * HD + 2 * k], Wih1[r * HD + 2 * k + 1]);
        bias = bih1[r] + bhh1[r];
    }
    // drain-lane (output head) setup
    const int dj = lane - 16;
    ull wlin2 = 0ull;
    if (layer == 0 && wl == 2 && lane >= 16 && dj < 10)
        wlin2 = pack2(Wlin[2 * dj], Wlin[2 * dj + 1]);
    const float blinsc = blin[0] * 0.01f;

    // ---- chunk ranges ----
    const int start_out = blockIdx.x * chl;
    if (start_out >= N) return;
    const int end_out = min(N, start_out + chl);
    const int s2      = max(0, start_out - CH_W);
    const int s1      = max(0, s2 - CH_W);
    const int span    = end_out - s1;

    // ---- preprocess grad -> (log, sign) features ----
    for (int i = tid; i < span; i += TPB) {
        float g  = grad[s1 + i];
        float lg = __logf(fabsf(g) + 1e-8f) * 0.1f;
        lg = fminf(1.f, fmaxf(-1.f, lg));
        float sg = fminf(1.f, fmaxf(-1.f, g * 22026.4657948067f)); // exp(10)
        xbuf[i] = make_float2(lg, sg);
    }
    if (tid < 32) {
        h0buf[0][tid] = 0.f; h0buf[1][tid] = 0.f;
        h1buf[0][tid] = 0.f; h1buf[1][tid] = 0.f;
    }
    __syncthreads();

    float cstate = 0.f, hlast = 0.f;
    float2 xv = xbuf[0];
    const int nIter = span + 2;

    #pragma unroll 2
    for (int i = 0; i < nIter; ++i) {
        const int tt = s1 + i;
        const int p  = tt & 1;

        if (layer == 0) {
            if ((wl < 2) | (lane < 16)) {            // row lanes
                if (tt < end_out) {
                    float base = fmaf(wx0, xv.x, fmaf(wx1, xv.y, bias));
                    const ulonglong2* hb = (const ulonglong2*)h0buf[p ^ 1];
                    ulonglong2 h0 = hb[0], h1 = hb[1], h2 = hb[2], h3 = hb[3], h4 = hb[4];
                    ull a0 = pack2(base, 0.f), a1 = 0ull, a2 = 0ull, a3 = 0ull;
                    a0 = ffma2(whh[0], h0.x, a0); a1 = ffma2(whh[1], h0.y, a1);
                    a2 = ffma2(whh[2], h1.x, a2); a3 = ffma2(whh[3], h1.y, a3);
                    a0 = ffma2(whh[4], h2.x, a0); a1 = ffma2(whh[5], h2.y, a1);
                    a2 = ffma2(whh[6], h3.x, a2); a3 = ffma2(whh[7], h3.y, a3);
                    a0 = ffma2(whh[8], h4.x, a0); a1 = ffma2(whh[9], h4.y, a1);
                    float2 f0 = unpack2(a0), f1 = unpack2(a1), f2 = unpack2(a2), f3 = unpack2(a3);
                    float pre = ((f0.x + f0.y) + (f1.x + f1.y)) + ((f2.x + f2.y) + (f3.x + f3.y));
                    float arg = (gate == 2) ? pre : 0.5f * pre;
                    float th  = tanh_fast(arg);
                    float aG  = (gate == 2) ? th : fmaf(th, 0.5f, 0.5f);
                    float v1 = __shfl_xor_sync(rmask, aG, 1);
                    float v2 = __shfl_xor_sync(rmask, aG, 2);
                    float v3 = __shfl_xor_sync(rmask, aG, 3);
                    cstate = fmaf(v1, cstate, aG * v2);
                    float hh = v3 * tanh_fast(cstate);
                    if (gate == 0) { hlast = hh; h0buf[p][u] = hh; }
                }
            } else {                                  // output-head lanes (w2, lane>=16)
                const int tout = tt - 2;
                if (tout >= start_out && tout < end_out) {
                    const int pp = tout & 1;
                    ull hv = ((const ull*)h1buf[pp])[dj];  // zeros beyond unit 20
                    float2 pf = unpack2(ffma2(wlin2, hv, 0ull));
                    float s = pf.x + pf.y;
                    s += __shfl_xor_sync(0xFFFF0000u, s, 1);
                    s += __shfl_xor_sync(0xFFFF0000u, s, 2);
                    s += __shfl_xor_sync(0xFFFF0000u, s, 4);
                    s += __shfl_xor_sync(0xFFFF0000u, s, 8);
                    if (lane == 16) out[tout] = fmaf(s, 0.01f, blinsc);
                }
            }
            xv = xbuf[i + 1];                         // prefetch (read-only buffer)
        } else {
            if (act) {
                const int t2 = tt - 1;
                if (t2 >= s2 && t2 < end_out) {
                    const int p2 = t2 & 1;
                    const ulonglong2* hb = (const ulonglong2*)h1buf[p2 ^ 1];
                    const ulonglong2* yb = (const ulonglong2*)h0buf[p2];
                    ulonglong2 h0 = hb[0], h1 = hb[1], h2 = hb[2], h3 = hb[3], h4 = hb[4];
                    ulonglong2 y0 = yb[0], y1 = yb[1], y2 = yb[2], y3 = yb[3], y4 = yb[4];
                    ull a0 = pack2(bias, 0.f), a1 = 0ull, a2 = 0ull, a3 = 0ull;
                    a0 = ffma2(whh[0], h0.x, a0); a1 = ffma2(whh[1], h0.y, a1);
                    a2 = ffma2(win[0], y0.x, a2); a3 = ffma2(win[1], y0.y, a3);
                    a0 = ffma2(whh[2], h1.x, a0); a1 = ffma2(whh[3], h1.y, a1);
                    a2 = ffma2(win[2], y1.x, a2); a3 = ffma2(win[3], y1.y, a3);
                    a0 = ffma2(whh[4], h2.x, a0); a1 = ffma2(whh[5], h2.y, a1);
                    a2 = ffma2(win[4], y2.x, a2); a3 = ffma2(win[5], y2.y, a3);
                    a0 = ffma2(whh[6], h3.x, a0); a1 = ffma2(whh[7], h3.y, a1);
                    a2 = ffma2(win[6], y3.x, a2); a3 = ffma2(win[7], y3.y, a3);
                    a0 = ffma2(whh[8], h4.x, a0); a1 = ffma2(whh[9], h4.y, a1);
                    a2 = ffma2(win[8], y4.x, a2); a3 = ffma2(win[9], y4.y, a3);
                    float2 f0 = unpack2(a0), f1 = unpack2(a1), f2 = unpack2(a2), f3 = unpack2(a3);
                    float pre = ((f0.x + f0.y) + (f1.x + f1.y)) + ((f2.x + f2.y) + (f3.x + f3.y));
                    float arg = (gate == 2) ? pre : 0.5f * pre;
                    float th  = tanh_fast(arg);
                    float aG  = (gate == 2) ? th : fmaf(th, 0.5f, 0.5f);
                    float v1 = __shfl_xor_sync(rmask, aG, 1);
                    float v2 = __shfl_xor_sync(rmask, aG, 2);
                    float v3 = __shfl_xor_sync(rmask, aG, 3);
                    cstate = fmaf(v1, cstate, aG * v2);
                    float hh = v3 * tanh_fast(cstate);
                    if (gate == 0) { hlast = hh; h1buf[p2][u] = hh; }
                }
            }
        }
        __syncthreads();
    }

    // final states: [update(N), h0(20), h1(20), c0(20), c1(20)]
    if (end_out == N && out_size >= N + 80 && gate == 0 && act) {
        if (layer == 0) { out[N + u]      = hlast; out[N + 40 + u] = cstate; }
        else            { out[N + 20 + u] = hlast; out[N + 60 + u] = cstate; }
    }
}

extern "C" void kernel_launch(void* const* d_in, const int* in_sizes, int n_in,
                              void* d_out, int out_size) {
    const float* grad = (const float*)d_in[0];
    const float* Wih0 = (const float*)d_in[1];
    const float* Whh0 = (const float*)d_in[2];
    const float* bih0 = (const float*)d_in[3];
    const float* bhh0 = (const float*)d_in[4];
    const float* Wih1 = (const float*)d_in[5];
    const float* Whh1 = (const float*)d_in[6];
    const float* bih1 = (const float*)d_in[7];
    const float* bhh1 = (const float*)d_in[8];
    const float* Wlin = (const float*)d_in[9];
    const float* blin = (const float*)d_in[10];

    int N = in_sizes[0];
    // target exactly 4 blocks per SM (148 SMs): grid ~= 592, uniform residency
    int chl = (N + 591) / 592;
    if (chl > XBUF_MAX - 2 * CH_W - 2) chl = XBUF_MAX - 2 * CH_W - 2;  // smem bound
    if (chl < 1) chl = 1;
    int grid = (N + chl - 1) / chl;
    lstm_opt_kernel<<<grid, TPB>>>(grad, Wih0, Whh0, bih0, bhh0,
                                   Wih1, Whh1, bih1, bhh1, Wlin, blin,
                                   (float*)d_out, N, out_size, chl);
}